// round 1
// baseline (speedup 1.0000x reference)
#include <cuda_runtime.h>

#define BB 32
#define SS 512
#define DD 768

// ---------------- scratch (static device globals; no allocations) ----------
__device__ float g_x1w[BB * SS * DD];     // 50 MB
__device__ float g_A  [BB * SS * SS];     // 33.5 MB
__device__ float g_P1 [BB * SS * SS];     // 33.5 MB
__device__ float g_P2 [BB * SS * SS];     // 33.5 MB
__device__ float g_rowmax[BB * SS];
__device__ float g_rowrs [BB * SS];
__device__ float g_colmax[BB * SS];
__device__ float g_colrs [BB * SS];
__device__ float g_bias1 [BB * SS];
__device__ float g_bias2 [BB * SS];

// ---------------- bias: bias1[b,s] = x1[b,s,:].W1 ; bias2[b,t] = x2[b,t,:].W2
__global__ void bias_kernel(const float* __restrict__ x1, const float* __restrict__ x2,
                            const float* __restrict__ W1, const float* __restrict__ W2)
{
    int warp = (blockIdx.x * blockDim.x + threadIdx.x) >> 5;
    int lane = threadIdx.x & 31;
    const int total = BB * SS;
    const float* x;
    const float* W;
    float* out;
    int row;
    if (warp < total) { x = x1; W = W1; out = g_bias1; row = warp; }
    else              { x = x2; W = W2; out = g_bias2; row = warp - total; }

    const float4* xr = (const float4*)(x + (long)row * DD);
    const float4* W4 = (const float4*)W;
    float s = 0.f;
    #pragma unroll
    for (int i = lane; i < DD / 4; i += 32) {
        float4 a = xr[i], w = W4[i];
        s += a.x * w.x + a.y * w.y + a.z * w.z + a.w * w.w;
    }
    #pragma unroll
    for (int o = 16; o; o >>= 1) s += __shfl_xor_sync(0xffffffffu, s, o);
    if (lane == 0) out[row] = s;
}

// ---------------- generic 64x64x16 tiled fp32 GEMM -------------------------
// C[M,N] = A[M,K] * B[K,N]  (all row-major).
// ATRANS: A-operand is stored K-major (Ag[k*lda + m]) -> used for P2^T @ x1.
// BIAS:   epilogue adds biasR[b*M+row] + biasC[b*N+col].
template <bool ATRANS, bool BIAS>
__global__ void __launch_bounds__(256) gemm64(
    const float* __restrict__ Ag, const float* __restrict__ Bg, float* __restrict__ Cg,
    int M, int N, int K, int lda, int ldb, int ldc,
    long sA, long sB, long sC,
    const float* __restrict__ biasR, const float* __restrict__ biasC)
{
    __shared__ float As[16][68];
    __shared__ float Bs[16][68];

    const int tid = threadIdx.x;
    const int tx = tid & 15, ty = tid >> 4;
    const int bm = blockIdx.y * 64, bn = blockIdx.x * 64;
    const int b = blockIdx.z;

    Ag += (long)b * sA;
    Bg += (long)b * sB;
    Cg += (long)b * sC;

    float acc[4][4] = {};

    for (int k0 = 0; k0 < K; k0 += 16) {
        if (ATRANS) {
            int kk = tid >> 4, m = (tid & 15) << 2;
            float4 v = *(const float4*)(Ag + (long)(k0 + kk) * lda + bm + m);
            *(float4*)&As[kk][m] = v;
        } else {
            int row = tid >> 2, kk = (tid & 3) << 2;
            float4 v = *(const float4*)(Ag + (long)(bm + row) * lda + k0 + kk);
            As[kk + 0][row] = v.x;
            As[kk + 1][row] = v.y;
            As[kk + 2][row] = v.z;
            As[kk + 3][row] = v.w;
        }
        {
            int kk = tid >> 4, n = (tid & 15) << 2;
            float4 v = *(const float4*)(Bg + (long)(k0 + kk) * ldb + bn + n);
            *(float4*)&Bs[kk][n] = v;
        }
        __syncthreads();

        #pragma unroll
        for (int kk = 0; kk < 16; kk++) {
            float a[4], bb[4];
            *(float4*)a  = *(const float4*)&As[kk][ty << 2];
            *(float4*)bb = *(const float4*)&Bs[kk][tx << 2];
            #pragma unroll
            for (int i = 0; i < 4; i++)
                #pragma unroll
                for (int j = 0; j < 4; j++)
                    acc[i][j] += a[i] * bb[j];
        }
        __syncthreads();
    }

    #pragma unroll
    for (int i = 0; i < 4; i++) {
        int row = bm + (ty << 2) + i;
        float br = BIAS ? biasR[b * M + row] : 0.f;
        #pragma unroll
        for (int j = 0; j < 4; j++) {
            int col = bn + (tx << 2) + j;
            float v = acc[i][j];
            if (BIAS) v += br + biasC[b * N + col];
            Cg[(long)row * ldc + col] = v;
        }
    }
}

// ---------------- softmax stats --------------------------------------------
// row stats: per (b,s) over t (axis=2 softmax -> P2)
__global__ void row_stats_kernel()
{
    int row = blockIdx.x;                    // b*SS + s
    const float4* a = (const float4*)(g_A + (long)row * SS);
    int tid = threadIdx.x;                   // 128 threads * 4 = 512
    float4 v = a[tid];
    float m = fmaxf(fmaxf(v.x, v.y), fmaxf(v.z, v.w));
    #pragma unroll
    for (int o = 16; o; o >>= 1) m = fmaxf(m, __shfl_xor_sync(0xffffffffu, m, o));
    __shared__ float sm[4], ssum[4];
    int w = tid >> 5, l = tid & 31;
    if (l == 0) sm[w] = m;
    __syncthreads();
    m = fmaxf(fmaxf(sm[0], sm[1]), fmaxf(sm[2], sm[3]));
    float s = __expf(v.x - m) + __expf(v.y - m) + __expf(v.z - m) + __expf(v.w - m);
    #pragma unroll
    for (int o = 16; o; o >>= 1) s += __shfl_xor_sync(0xffffffffu, s, o);
    if (l == 0) ssum[w] = s;
    __syncthreads();
    s = ssum[0] + ssum[1] + ssum[2] + ssum[3];
    if (tid == 0) { g_rowmax[row] = m; g_rowrs[row] = 1.0f / s; }
}

// col stats: per (b,t) over s (axis=1 softmax -> P1)
__global__ void col_stats_kernel()
{
    int b = blockIdx.x >> 2;
    int t = ((blockIdx.x & 3) << 7) + threadIdx.x;
    const float* a = g_A + (long)b * SS * SS + t;
    float m = -1e30f;
    #pragma unroll 8
    for (int s = 0; s < SS; s++) m = fmaxf(m, a[(long)s * SS]);
    float sum = 0.f;
    #pragma unroll 8
    for (int s = 0; s < SS; s++) sum += __expf(a[(long)s * SS] - m);
    g_colmax[b * SS + t] = m;
    g_colrs [b * SS + t] = 1.0f / sum;
}

// P1[s,t] = exp(A - colmax[t]) / colsum[t]   (softmax over axis=1)
// P2[s,t] = exp(A - rowmax[s]) / rowsum[s]   (softmax over axis=2)
__global__ void prob_kernel()
{
    int i = blockIdx.x * 256 + threadIdx.x;   // float4 index, total BB*SS*SS/4
    int e = i << 2;
    int b = e / (SS * SS);
    int r = e % (SS * SS);
    int s = r >> 9;
    int t = r & 511;

    float4 v = ((const float4*)g_A)[i];
    float rm = g_rowmax[b * SS + s];
    float rr = g_rowrs [b * SS + s];
    int ci = (b * SS + t) >> 2;
    float4 cm = ((const float4*)g_colmax)[ci];
    float4 cr = ((const float4*)g_colrs)[ci];

    float4 p1, p2;
    p1.x = __expf(v.x - cm.x) * cr.x;
    p1.y = __expf(v.y - cm.y) * cr.y;
    p1.z = __expf(v.z - cm.z) * cr.z;
    p1.w = __expf(v.w - cm.w) * cr.w;
    p2.x = __expf(v.x - rm) * rr;
    p2.y = __expf(v.y - rm) * rr;
    p2.z = __expf(v.z - rm) * rr;
    p2.w = __expf(v.w - rm) * rr;

    ((float4*)g_P1)[i] = p1;
    ((float4*)g_P2)[i] = p2;
}

// ---------------- launch -----------------------------------------------------
extern "C" void kernel_launch(void* const* d_in, const int* in_sizes, int n_in,
                              void* d_out, int out_size)
{
    const float* x1 = (const float*)d_in[0];
    const float* x2 = (const float*)d_in[1];
    const float* Wc = (const float*)d_in[2];
    const float* W1 = (const float*)d_in[3];
    const float* W2 = (const float*)d_in[4];
    float* out1 = (float*)d_out;
    float* out2 = out1 + (long)BB * SS * DD;

    float *p_x1w, *p_A, *p_P1, *p_P2, *p_b1, *p_b2;
    cudaGetSymbolAddress((void**)&p_x1w, g_x1w);
    cudaGetSymbolAddress((void**)&p_A,   g_A);
    cudaGetSymbolAddress((void**)&p_P1,  g_P1);
    cudaGetSymbolAddress((void**)&p_P2,  g_P2);
    cudaGetSymbolAddress((void**)&p_b1,  g_bias1);
    cudaGetSymbolAddress((void**)&p_b2,  g_bias2);

    const long sSD = (long)SS * DD;
    const long sSSq = (long)SS * SS;

    // K1: x1w = x1 @ Wc   [512x768x768], Wc shared across batch
    gemm64<false, false><<<dim3(DD / 64, SS / 64, BB), 256>>>(
        x1, Wc, p_x1w, SS, DD, DD, DD, DD, DD, sSD, 0, sSD, nullptr, nullptr);

    // bias terms (independent of K1)
    bias_kernel<<<(2 * BB * SS) / 8, 256>>>(x1, x2, W1, W2);

    // K3: A = x1w @ reshape(x2,[B,D,S]) + bias1 + bias2   [512x512x768]
    // B-operand is x2 memory viewed [D,S] row-major (ld = S).
    gemm64<false, true><<<dim3(SS / 64, SS / 64, BB), 256>>>(
        p_x1w, x2, p_A, SS, SS, DD, DD, SS, SS, sSD, sSD, sSSq, p_b1, p_b2);

    // softmax stats
    row_stats_kernel<<<BB * SS, 128>>>();
    col_stats_kernel<<<BB * 4, 128>>>();

    // probabilities
    prob_kernel<<<(BB * SS * SS / 4) / 256, 256>>>();

    // K5: f_x1 = P1 @ x2   [512x768x512]
    gemm64<false, false><<<dim3(DD / 64, SS / 64, BB), 256>>>(
        p_P1, x2, out1, SS, DD, SS, SS, DD, DD, sSSq, sSD, sSD, nullptr, nullptr);

    // K6: f_x2 = P2^T @ x1   [512x768x512], A-operand K-major (P2 is [s][t] = [K][M])
    gemm64<true, false><<<dim3(DD / 64, SS / 64, BB), 256>>>(
        p_P2, x1, out2, SS, DD, SS, SS, DD, DD, sSSq, sSD, sSD, nullptr, nullptr);
}

// round 3
// speedup vs baseline: 2.0789x; 2.0789x over previous
#include <cuda_runtime.h>
#include <cuda_bf16.h>
#include <cstdint>

#define BB 32
#define SS 512
#define DD 768

static const long N_SD = (long)BB * SS * DD;   // 12,582,912

// ---------------- scratch (static device globals; no allocations) ----------
__device__ __nv_bfloat16 g_x1h [BB * SS * DD];
__device__ __nv_bfloat16 g_x1l [BB * SS * DD];
__device__ __nv_bfloat16 g_WcTh[DD * DD];
__device__ __nv_bfloat16 g_WcTl[DD * DD];
__device__ __nv_bfloat16 g_x2rh[BB * SS * DD];   // [t][e] = x2flat[e*S+t]
__device__ __nv_bfloat16 g_x2rl[BB * SS * DD];
__device__ __nv_bfloat16 g_x2Th[BB * DD * SS];   // [d][t] = x2[t][d]
__device__ __nv_bfloat16 g_x2Tl[BB * DD * SS];
__device__ __nv_bfloat16 g_x1Th[BB * DD * SS];   // [d][s] = x1[s][d]
__device__ __nv_bfloat16 g_x1Tl[BB * DD * SS];
__device__ __nv_bfloat16 g_x1wh[BB * SS * DD];
__device__ __nv_bfloat16 g_x1wl[BB * SS * DD];
__device__ __nv_bfloat16 g_P1h [BB * SS * SS];
__device__ __nv_bfloat16 g_P1l [BB * SS * SS];
__device__ __nv_bfloat16 g_P2Th[BB * SS * SS];   // [t][s]
__device__ __nv_bfloat16 g_P2Tl[BB * SS * SS];
__device__ float g_A  [BB * SS * SS];            // fp32 logits
__device__ float g_rowmax[BB * SS];
__device__ float g_rowrs [BB * SS];
__device__ float g_colmax[BB * SS];
__device__ float g_colrs [BB * SS];
__device__ float g_bias1 [BB * SS];
__device__ float g_bias2 [BB * SS];

// ---------------- helpers ----------------------------------------------------
__device__ __forceinline__ uint32_t smem_to_u32(const void* p) {
    uint32_t a;
    asm("{ .reg .u64 t; cvta.to.shared.u64 t, %1; cvt.u32.u64 %0, t; }" : "=r"(a) : "l"(p));
    return a;
}
__device__ __forceinline__ void cp_async16(uint32_t dst, const void* src) {
    asm volatile("cp.async.cg.shared.global [%0], [%1], 16;" :: "r"(dst), "l"(src));
}
__device__ __forceinline__ void ldsm_x4(uint32_t* r, uint32_t addr) {
    asm volatile("ldmatrix.sync.aligned.m8n8.x4.shared.b16 {%0,%1,%2,%3}, [%4];"
                 : "=r"(r[0]), "=r"(r[1]), "=r"(r[2]), "=r"(r[3]) : "r"(addr));
}
__device__ __forceinline__ void mma16816(float* d, const uint32_t* a, const uint32_t* b) {
    asm volatile(
        "mma.sync.aligned.m16n8k16.row.col.f32.bf16.bf16.f32 "
        "{%0,%1,%2,%3}, {%4,%5,%6,%7}, {%8,%9}, {%0,%1,%2,%3};"
        : "+f"(d[0]), "+f"(d[1]), "+f"(d[2]), "+f"(d[3])
        : "r"(a[0]), "r"(a[1]), "r"(a[2]), "r"(a[3]), "r"(b[0]), "r"(b[1]));
}

union Pack4 { __nv_bfloat16 b[4]; uint2 u; };
__device__ __forceinline__ void split1(float v, __nv_bfloat16& h, __nv_bfloat16& l) {
    h = __float2bfloat16_rn(v);
    l = __float2bfloat16_rn(v - __bfloat162float(h));
}

// ---------------- convert: fp32 -> bf16 hi/lo (elementwise) ------------------
__global__ void conv_hl(const float4* __restrict__ in,
                        __nv_bfloat16* __restrict__ oh, __nv_bfloat16* __restrict__ ol)
{
    long i = (long)blockIdx.x * 256 + threadIdx.x;
    float4 v = in[i];
    Pack4 h, l;
    split1(v.x, h.b[0], l.b[0]);
    split1(v.y, h.b[1], l.b[1]);
    split1(v.z, h.b[2], l.b[2]);
    split1(v.w, h.b[3], l.b[3]);
    ((uint2*)oh)[i] = h.u;
    ((uint2*)ol)[i] = l.u;
}

// ---------------- transpose + split: in[R][C] -> out[C][R] hi/lo -------------
__global__ void transpose_hl(const float* __restrict__ in, long sIn, int R, int C,
                             __nv_bfloat16* __restrict__ oh, __nv_bfloat16* __restrict__ ol,
                             long sOut)
{
    __shared__ float t[32][33];
    in += (long)blockIdx.z * sIn;
    oh += (long)blockIdx.z * sOut;
    ol += (long)blockIdx.z * sOut;
    int c0 = blockIdx.x * 32, r0 = blockIdx.y * 32;
    int tx = threadIdx.x & 31, ty = threadIdx.x >> 5;  // 256 threads -> ty 0..7
    #pragma unroll
    for (int j = 0; j < 4; j++)
        t[ty + j * 8][tx] = in[(long)(r0 + ty + j * 8) * C + c0 + tx];
    __syncthreads();
    int c = threadIdx.x >> 3, g = threadIdx.x & 7;
    int rr = g * 4;
    Pack4 h, l;
    #pragma unroll
    for (int q = 0; q < 4; q++) split1(t[rr + q][c], h.b[q], l.b[q]);
    *(uint2*)(oh + (long)(c0 + c) * R + r0 + rr) = h.u;
    *(uint2*)(ol + (long)(c0 + c) * R + r0 + rr) = l.u;
}

// ---------------- bias: bias1[b,s] = x1[b,s,:].W1 ; bias2[b,t] = x2[b,t,:].W2
__global__ void bias_kernel(const float* __restrict__ x1, const float* __restrict__ x2,
                            const float* __restrict__ W1, const float* __restrict__ W2)
{
    int warp = (blockIdx.x * blockDim.x + threadIdx.x) >> 5;
    int lane = threadIdx.x & 31;
    const int total = BB * SS;
    const float* x; const float* W; float* out; int row;
    if (warp < total) { x = x1; W = W1; out = g_bias1; row = warp; }
    else              { x = x2; W = W2; out = g_bias2; row = warp - total; }
    const float4* xr = (const float4*)(x + (long)row * DD);
    const float4* W4 = (const float4*)W;
    float s = 0.f;
    #pragma unroll
    for (int i = lane; i < DD / 4; i += 32) {
        float4 a = xr[i], w = W4[i];
        s += a.x * w.x + a.y * w.y + a.z * w.z + a.w * w.w;
    }
    #pragma unroll
    for (int o = 16; o; o >>= 1) s += __shfl_xor_sync(0xffffffffu, s, o);
    if (lane == 0) out[row] = s;
}

// ---------------- mma.sync split-bf16 GEMM -----------------------------------
// C[m][n] = sum_k (Ah+Al)[m][k]*(Bh+Bl)[n][k]  (3-term: hh + hl + lh)
// Block tile 128x128, BK=32, 8 warps (2M x 4N), warp tile 64x32.
// EPI 0: fp32 C.  EPI 1: bf16 hi/lo C.  EPI 2: fp32 C + biasR + biasC.
#define STRIDE40 40                    // bf16 per smem row (pad 32 -> 40)
#define TILEB   (128 * STRIDE40 * 2)   // 10240 B
#define STAGEB  (4 * TILEB)            // 40960 B
#define SMEM_GEMM (2 * STAGEB)         // 81920 B

template <int EPI>
__global__ void __launch_bounds__(256) gemm_tc(
    const __nv_bfloat16* __restrict__ Ah, const __nv_bfloat16* __restrict__ Al, long sA, int lda,
    const __nv_bfloat16* __restrict__ Bh, const __nv_bfloat16* __restrict__ Bl, long sB, int ldb,
    int K,
    float* __restrict__ C, __nv_bfloat16* __restrict__ Ch, __nv_bfloat16* __restrict__ Cl,
    long sC, int ldc,
    const float* __restrict__ biasR, const float* __restrict__ biasC, int Mtot, int Ntot)
{
    extern __shared__ char smem[];
    const uint32_t sbase = smem_to_u32(smem);
    const int tid = threadIdx.x;
    const int lane = tid & 31;
    const int wm = (tid >> 5) >> 2, wn = (tid >> 5) & 3;
    const int bm = blockIdx.y * 128, bn = blockIdx.x * 128, bz = blockIdx.z;

    const __nv_bfloat16* a0 = Ah + (long)bz * sA;
    const __nv_bfloat16* a1 = Al + (long)bz * sA;
    const __nv_bfloat16* b0 = Bh + (long)bz * sB;
    const __nv_bfloat16* b1 = Bl + (long)bz * sB;

    const int ldrow = tid >> 2;          // 0..63
    const int lds   = tid & 3;           // 16B seg within 64B chunk

    float acc[4][4][4];
    #pragma unroll
    for (int i = 0; i < 4; i++)
        #pragma unroll
        for (int j = 0; j < 4; j++)
            #pragma unroll
            for (int q = 0; q < 4; q++) acc[i][j][q] = 0.f;

    const int NC = K >> 5;

    // ---- stage loader: q in 0..7, tile = q>>1 (compile-time), row = (q&1)*64 + tid/4
    #define LOAD_STAGE(cc, st) do {                                            \
        uint32_t dst0 = sbase + (st) * STAGEB;                                 \
        int k0 = (cc) << 5;                                                    \
        _Pragma("unroll")                                                      \
        for (int q = 0; q < 8; q++) {                                          \
            const int t4 = q >> 1;                                             \
            const int row = ((q & 1) << 6) + ldrow;                            \
            const __nv_bfloat16* sp = (t4 == 0) ? a0 : (t4 == 1) ? a1          \
                                     : (t4 == 2) ? b0 : b1;                    \
            const int rb = (t4 < 2) ? bm : bn;                                 \
            const int ld = (t4 < 2) ? lda : ldb;                               \
            cp_async16(dst0 + t4 * TILEB + row * (STRIDE40 * 2) + lds * 16,    \
                       sp + (long)(rb + row) * ld + k0 + lds * 8);             \
        }                                                                      \
        asm volatile("cp.async.commit_group;");                               \
    } while (0)

    LOAD_STAGE(0, 0);

    const int lr = lane & 15;
    const int lc = (lane >> 4) << 3;

    for (int c = 0; c < NC; c++) {
        if (c + 1 < NC) {
            LOAD_STAGE(c + 1, (c + 1) & 1);
            asm volatile("cp.async.wait_group 1;");
        } else {
            asm volatile("cp.async.wait_group 0;");
        }
        __syncthreads();

        uint32_t sAh = sbase + (c & 1) * STAGEB;
        uint32_t sAl = sAh + TILEB;
        uint32_t sBh = sAh + 2 * TILEB;
        uint32_t sBl = sAh + 3 * TILEB;

        #pragma unroll
        for (int kk = 0; kk < 2; kk++) {
            uint32_t fa_h[4][4], fa_l[4][4];
            #pragma unroll
            for (int mm = 0; mm < 4; mm++) {
                uint32_t off = (uint32_t)(wm * 64 + mm * 16 + lr) * (STRIDE40 * 2)
                             + (uint32_t)(kk * 16 + lc) * 2;
                ldsm_x4(fa_h[mm], sAh + off);
                ldsm_x4(fa_l[mm], sAl + off);
            }
            uint32_t fb_h[2][4], fb_l[2][4];
            #pragma unroll
            for (int nn = 0; nn < 2; nn++) {
                uint32_t off = (uint32_t)(wn * 32 + nn * 16 + lr) * (STRIDE40 * 2)
                             + (uint32_t)(kk * 16 + lc) * 2;
                ldsm_x4(fb_h[nn], sBh + off);
                ldsm_x4(fb_l[nn], sBl + off);
            }
            #pragma unroll
            for (int mm = 0; mm < 4; mm++) {
                #pragma unroll
                for (int nt = 0; nt < 4; nt++) {
                    uint32_t bh2[2] = { fb_h[nt >> 1][nt & 1], fb_h[nt >> 1][(nt & 1) + 2] };
                    uint32_t bl2[2] = { fb_l[nt >> 1][nt & 1], fb_l[nt >> 1][(nt & 1) + 2] };
                    mma16816(acc[mm][nt], fa_h[mm], bh2);
                    mma16816(acc[mm][nt], fa_h[mm], bl2);
                    mma16816(acc[mm][nt], fa_l[mm], bh2);
                }
            }
        }
        __syncthreads();
    }

    // ---- epilogue
    const int er0 = bm + wm * 64 + (lane >> 2);
    const int ec0 = bn + wn * 32 + ((lane & 3) << 1);
    #pragma unroll
    for (int mm = 0; mm < 4; mm++) {
        #pragma unroll
        for (int nt = 0; nt < 4; nt++) {
            int row = er0 + mm * 16;
            int col = ec0 + nt * 8;
            float v0 = acc[mm][nt][0], v1 = acc[mm][nt][1];
            float v2 = acc[mm][nt][2], v3 = acc[mm][nt][3];
            if (EPI == 1) {
                __nv_bfloat16 h0, l0, h1, l1;
                long o = (long)bz * sC + (long)row * ldc + col;
                split1(v0, h0, l0); split1(v1, h1, l1);
                *(__nv_bfloat162*)(Ch + o) = __nv_bfloat162(h0, h1);
                *(__nv_bfloat162*)(Cl + o) = __nv_bfloat162(l0, l1);
                o += (long)8 * ldc;
                split1(v2, h0, l0); split1(v3, h1, l1);
                *(__nv_bfloat162*)(Ch + o) = __nv_bfloat162(h0, h1);
                *(__nv_bfloat162*)(Cl + o) = __nv_bfloat162(l0, l1);
            } else {
                if (EPI == 2) {
                    float bc0 = biasC[bz * Ntot + col], bc1 = biasC[bz * Ntot + col + 1];
                    float br0 = biasR[bz * Mtot + row], br8 = biasR[bz * Mtot + row + 8];
                    v0 += br0 + bc0; v1 += br0 + bc1;
                    v2 += br8 + bc0; v3 += br8 + bc1;
                }
                long o = (long)bz * sC + (long)row * ldc + col;
                *(float2*)(C + o) = make_float2(v0, v1);
                *(float2*)(C + o + (long)8 * ldc) = make_float2(v2, v3);
            }
        }
    }
}

// ---------------- softmax stats ---------------------------------------------
__global__ void row_stats_kernel()
{
    int row = blockIdx.x;
    const float4* a = (const float4*)(g_A + (long)row * SS);
    int tid = threadIdx.x;
    float4 v = a[tid];
    float m = fmaxf(fmaxf(v.x, v.y), fmaxf(v.z, v.w));
    #pragma unroll
    for (int o = 16; o; o >>= 1) m = fmaxf(m, __shfl_xor_sync(0xffffffffu, m, o));
    __shared__ float sm[4], ssum[4];
    int w = tid >> 5, l = tid & 31;
    if (l == 0) sm[w] = m;
    __syncthreads();
    m = fmaxf(fmaxf(sm[0], sm[1]), fmaxf(sm[2], sm[3]));
    float s = __expf(v.x - m) + __expf(v.y - m) + __expf(v.z - m) + __expf(v.w - m);
    #pragma unroll
    for (int o = 16; o; o >>= 1) s += __shfl_xor_sync(0xffffffffu, s, o);
    if (l == 0) ssum[w] = s;
    __syncthreads();
    s = ssum[0] + ssum[1] + ssum[2] + ssum[3];
    if (tid == 0) { g_rowmax[row] = m; g_rowrs[row] = 1.0f / s; }
}

__global__ void col_stats_kernel()
{
    int b = blockIdx.x >> 2;
    int t = ((blockIdx.x & 3) << 7) + threadIdx.x;
    const float* a = g_A + (long)b * SS * SS + t;
    float m = -1e30f;
    #pragma unroll 8
    for (int s = 0; s < SS; s++) m = fmaxf(m, a[(long)s * SS]);
    float sum = 0.f;
    #pragma unroll 8
    for (int s = 0; s < SS; s++) sum += __expf(a[(long)s * SS] - m);
    g_colmax[b * SS + t] = m;
    g_colrs [b * SS + t] = 1.0f / sum;
}

// ---------------- probabilities: P1 (hi/lo) and P2^T (hi/lo) -----------------
__global__ void prob_kernel()
{
    __shared__ float p2t[64 * 65];
    int b = blockIdx.z;
    int bs0 = blockIdx.y * 64, bt0 = blockIdx.x * 64;
    const float* A = g_A + (long)b * SS * SS;
    int tid = threadIdx.x;

    #pragma unroll
    for (int it = 0; it < 4; it++) {
        int idx = tid + it * 256;
        int r = idx >> 4, c4 = idx & 15;
        int s = bs0 + r;
        float4 v = *(const float4*)(A + (long)s * SS + bt0 + c4 * 4);
        float rm = g_rowmax[b * SS + s];
        float rr = g_rowrs [b * SS + s];
        const float4 cm = *(const float4*)(g_colmax + b * SS + bt0 + c4 * 4);
        const float4 cr = *(const float4*)(g_colrs  + b * SS + bt0 + c4 * 4);
        float p1v[4] = { __expf(v.x - cm.x) * cr.x, __expf(v.y - cm.y) * cr.y,
                         __expf(v.z - cm.z) * cr.z, __expf(v.w - cm.w) * cr.w };
        float p2v[4] = { __expf(v.x - rm) * rr, __expf(v.y - rm) * rr,
                         __expf(v.z - rm) * rr, __expf(v.w - rm) * rr };
        Pack4 h, l;
        #pragma unroll
        for (int q = 0; q < 4; q++) split1(p1v[q], h.b[q], l.b[q]);
        long o1 = (long)b * SS * SS + (long)s * SS + bt0 + c4 * 4;
        *(uint2*)(g_P1h + o1) = h.u;
        *(uint2*)(g_P1l + o1) = l.u;
        #pragma unroll
        for (int q = 0; q < 4; q++) p2t[(c4 * 4 + q) * 65 + r] = p2v[q];
    }
    __syncthreads();
    int c = tid >> 2, g = tid & 3;
    #pragma unroll
    for (int j = 0; j < 4; j++) {
        int rr0 = g * 16 + j * 4;
        Pack4 h, l;
        #pragma unroll
        for (int q = 0; q < 4; q++) split1(p2t[c * 65 + rr0 + q], h.b[q], l.b[q]);
        long o = (long)b * SS * SS + (long)(bt0 + c) * SS + bs0 + rr0;
        *(uint2*)(g_P2Th + o) = h.u;
        *(uint2*)(g_P2Tl + o) = l.u;
    }
}

// ---------------- launch -----------------------------------------------------
extern "C" void kernel_launch(void* const* d_in, const int* in_sizes, int n_in,
                              void* d_out, int out_size)
{
    const float* x1 = (const float*)d_in[0];
    const float* x2 = (const float*)d_in[1];
    const float* Wc = (const float*)d_in[2];
    const float* W1 = (const float*)d_in[3];
    const float* W2 = (const float*)d_in[4];
    float* out1 = (float*)d_out;
    float* out2 = out1 + N_SD;

    __nv_bfloat16 *x1h, *x1l, *WcTh, *WcTl, *x2rh, *x2rl, *x2Th, *x2Tl, *x1Th, *x1Tl;
    __nv_bfloat16 *x1wh, *x1wl, *P1h, *P1l, *P2Th, *P2Tl;
    float *pA, *pb1, *pb2;
    cudaGetSymbolAddress((void**)&x1h,  g_x1h);
    cudaGetSymbolAddress((void**)&x1l,  g_x1l);
    cudaGetSymbolAddress((void**)&WcTh, g_WcTh);
    cudaGetSymbolAddress((void**)&WcTl, g_WcTl);
    cudaGetSymbolAddress((void**)&x2rh, g_x2rh);
    cudaGetSymbolAddress((void**)&x2rl, g_x2rl);
    cudaGetSymbolAddress((void**)&x2Th, g_x2Th);
    cudaGetSymbolAddress((void**)&x2Tl, g_x2Tl);
    cudaGetSymbolAddress((void**)&x1Th, g_x1Th);
    cudaGetSymbolAddress((void**)&x1Tl, g_x1Tl);
    cudaGetSymbolAddress((void**)&x1wh, g_x1wh);
    cudaGetSymbolAddress((void**)&x1wl, g_x1wl);
    cudaGetSymbolAddress((void**)&P1h,  g_P1h);
    cudaGetSymbolAddress((void**)&P1l,  g_P1l);
    cudaGetSymbolAddress((void**)&P2Th, g_P2Th);
    cudaGetSymbolAddress((void**)&P2Tl, g_P2Tl);
    cudaGetSymbolAddress((void**)&pA,   g_A);
    cudaGetSymbolAddress((void**)&pb1,  g_bias1);
    cudaGetSymbolAddress((void**)&pb2,  g_bias2);

    cudaFuncSetAttribute(gemm_tc<0>, cudaFuncAttributeMaxDynamicSharedMemorySize, SMEM_GEMM);
    cudaFuncSetAttribute(gemm_tc<1>, cudaFuncAttributeMaxDynamicSharedMemorySize, SMEM_GEMM);
    cudaFuncSetAttribute(gemm_tc<2>, cudaFuncAttributeMaxDynamicSharedMemorySize, SMEM_GEMM);

    const long sSD = (long)SS * DD;
    const long sSq = (long)SS * SS;

    // converts / transposes
    conv_hl<<<(int)(N_SD / 4 / 256), 256>>>((const float4*)x1, x1h, x1l);
    transpose_hl<<<dim3(DD / 32, DD / 32, 1), 256>>>(Wc, 0, DD, DD, WcTh, WcTl, 0);
    transpose_hl<<<dim3(SS / 32, DD / 32, BB), 256>>>(x2, sSD, DD, SS, x2rh, x2rl, sSD);
    transpose_hl<<<dim3(DD / 32, SS / 32, BB), 256>>>(x2, sSD, SS, DD, x2Th, x2Tl, sSD);
    transpose_hl<<<dim3(DD / 32, SS / 32, BB), 256>>>(x1, sSD, SS, DD, x1Th, x1Tl, sSD);
    bias_kernel<<<(2 * BB * SS) / 8, 256>>>(x1, x2, W1, W2);

    // G1: x1w = x1 @ Wc  (M=512, N=768, K=768) -> bf16 hi/lo epilogue
    gemm_tc<1><<<dim3(DD / 128, SS / 128, BB), 256, SMEM_GEMM>>>(
        x1h, x1l, sSD, DD, WcTh, WcTl, 0, DD, DD,
        nullptr, x1wh, x1wl, sSD, DD, nullptr, nullptr, SS, DD);

    // G3: A = x1w @ x2r^T + biases  (M=512, N=512, K=768) -> fp32 + bias
    gemm_tc<2><<<dim3(SS / 128, SS / 128, BB), 256, SMEM_GEMM>>>(
        x1wh, x1wl, sSD, DD, x2rh, x2rl, sSD, DD, DD,
        pA, nullptr, nullptr, sSq, SS, pb1, pb2, SS, SS);

    row_stats_kernel<<<BB * SS, 128>>>();
    col_stats_kernel<<<BB * 4, 128>>>();
    prob_kernel<<<dim3(SS / 64, SS / 64, BB), 256>>>();

    // G5: f_x1 = P1 @ x2  (M=512, N=768, K=512)
    gemm_tc<0><<<dim3(DD / 128, SS / 128, BB), 256, SMEM_GEMM>>>(
        P1h, P1l, sSq, SS, x2Th, x2Tl, sSD, SS, SS,
        out1, nullptr, nullptr, sSD, DD, nullptr, nullptr, SS, DD);

    // G6: f_x2 = P2^T @ x1  (M=512, N=768, K=512)
    gemm_tc<0><<<dim3(DD / 128, SS / 128, BB), 256, SMEM_GEMM>>>(
        P2Th, P2Tl, sSq, SS, x1Th, x1Tl, sSD, SS, SS,
        out2, nullptr, nullptr, sSD, DD, nullptr, nullptr, SS, DD);
}